// round 9
// baseline (speedup 1.0000x reference)
#include <cuda_runtime.h>
#include <cuda_fp16.h>
#include <cstdint>
#include <cstddef>

#define BATCH 2
#define SEQ   2048
#define HID   4096
#define NH    32
#define KVH   8
#define HD    128
#define MTOT  (BATCH*SEQ)      // 4096
#define KVD   (KVH*HD)         // 1024
#define QKVW  (HID + 2*KVD)    // 6144 packed width

#define CDIV(a,b) (((a)+(b)-1)/(b))

// ---------------- scratch (allocation-free: __device__ globals) ----------------
__device__ __half g_Ah  [MTOT*HID];        // fp16(hidden)               32 MB
__device__ __half g_Wh  [QKVW*HID];        // packed Wq|Wk|Wv            48 MB
__device__ __half g_Woh [HID*HID];         //                            32 MB
__device__ __half g_QKVh[MTOT*QKVW];       // packed Q|K|V               48 MB
__device__ __half g_Oh  [MTOT*HID];        //                            32 MB
__device__ float  g_cos[SEQ*64];
__device__ float  g_sin[SEQ*64];

// ---------------- helpers ----------------
static __device__ __forceinline__ uint32_t smem_u32(const void* p) {
    uint32_t a;
    asm("{ .reg .u64 t; cvta.to.shared.u64 t, %1; cvt.u32.u64 %0, t; }" : "=r"(a) : "l"(p));
    return a;
}

static __device__ __forceinline__ void mma_f16(float* d, const uint32_t* a, const uint32_t* b) {
    asm volatile(
        "mma.sync.aligned.m16n8k16.row.col.f32.f16.f16.f32 "
        "{%0,%1,%2,%3}, {%4,%5,%6,%7}, {%8,%9}, {%0,%1,%2,%3};\n"
        : "+f"(d[0]), "+f"(d[1]), "+f"(d[2]), "+f"(d[3])
        : "r"(a[0]), "r"(a[1]), "r"(a[2]), "r"(a[3]),
          "r"(b[0]), "r"(b[1]));
}

static __device__ __forceinline__ void ldsm_x4(uint32_t* r, uint32_t addr) {
    asm volatile("ldmatrix.sync.aligned.m8n8.x4.shared.b16 {%0,%1,%2,%3}, [%4];"
                 : "=r"(r[0]), "=r"(r[1]), "=r"(r[2]), "=r"(r[3]) : "r"(addr));
}
static __device__ __forceinline__ void ldsm_x4t(uint32_t* r, uint32_t addr) {
    asm volatile("ldmatrix.sync.aligned.m8n8.x4.trans.shared.b16 {%0,%1,%2,%3}, [%4];"
                 : "=r"(r[0]), "=r"(r[1]), "=r"(r[2]), "=r"(r[3]) : "r"(addr));
}

static __device__ __forceinline__ void cp_async16(uint32_t dst, const void* src) {
    asm volatile("cp.async.cg.shared.global [%0], [%1], 16;" :: "r"(dst), "l"(src));
}
static __device__ __forceinline__ void cp_commit() {
    asm volatile("cp.async.commit_group;" ::: "memory");
}
template<int N> static __device__ __forceinline__ void cp_wait() {
    asm volatile("cp.async.wait_group %0;" :: "n"(N) : "memory");
}

static __device__ __forceinline__ uint32_t pack_h2(float a, float b) {
    __half2 h = __floats2half2_rn(a, b);
    return *reinterpret_cast<uint32_t*>(&h);
}

// ---------------- fp32 -> fp16 convert (8 elts/thread) ----------------
__global__ void f2h_kernel(const float4* __restrict__ in, uint4* __restrict__ out, int n8) {
    int i = blockIdx.x * blockDim.x + threadIdx.x;
    if (i >= n8) return;
    float4 a = in[2*i], b = in[2*i+1];
    uint4 o;
    o.x = pack_h2(a.x, a.y); o.y = pack_h2(a.z, a.w);
    o.z = pack_h2(b.x, b.y); o.w = pack_h2(b.z, b.w);
    out[i] = o;
}

// ---------------- RoPE ----------------
__global__ void rope_table_kernel(const int* __restrict__ pos,
                                  float* __restrict__ ct, float* __restrict__ st) {
    int s = blockIdx.x;
    int i = threadIdx.x;             // 0..63
    double inv = exp(-9.210340371976184 * (double)i / 64.0);  // 10000^(-2i/128)
    double ang = (double)pos[s] * inv;
    ct[s*64 + i] = (float)cos(ang);
    st[s*64 + i] = (float)sin(ang);
}

// RoPE on packed QKV buffer [MTOT, QKVW]; colbase selects Q (0) or K (HID) region
__global__ void rope_qkv_kernel(__half* __restrict__ X, const float* __restrict__ ct,
                                const float* __restrict__ st, int nh, int colbase, int total) {
    int idx = blockIdx.x * blockDim.x + threadIdx.x;
    if (idx >= total) return;
    int i   = idx & 63;
    int h   = (idx >> 6) % nh;
    int row = idx / (64 * nh);        // b*SEQ + s
    int s   = row & (SEQ - 1);
    float c  = ct[s*64 + i];
    float sn = st[s*64 + i];
    size_t base = (size_t)row * QKVW + colbase + h * 128 + i;
    float x1 = __half2float(X[base]);
    float x2 = __half2float(X[base + 64]);
    X[base]      = __float2half_rn(x1 * c - x2 * sn);
    X[base + 64] = __float2half_rn(x2 * c + x1 * sn);
}

// ============== fp16 tensor-core GEMM: C[M,N] = A[M,K] * B[N,K]^T ==============
// CTA 128x256, 8 warps (2x4) of 64x64, BK=32, 4-stage cp.async, ldmatrix frags.
#define GBM 128
#define GBN 256
#define GBK 32
#define GSTG 4
#define GST 40                               // halves per row (32 + 8 pad)
#define A_BYTES (GBM*GST*2)                  // 10240
#define B_BYTES (GBN*GST*2)                  // 20480
#define STG_BYTES (A_BYTES + B_BYTES)        // 30720
#define GEMM_SMEM (GSTG*STG_BYTES)           // 122880

template<bool HALF_OUT>
__global__ __launch_bounds__(256, 1)
void gemm_h(const __half* __restrict__ A, const __half* __restrict__ B,
            void* __restrict__ Cout, int N, int K) {
    extern __shared__ char smem[];
    const uint32_t sb = smem_u32(smem);
    const int tid = threadIdx.x, lane = tid & 31, warp = tid >> 5;
    const int wm = warp >> 2, wn = warp & 3;          // 2 x 4
    const int g = lane >> 2, tig = lane & 3;
    const int bm0 = blockIdx.y * GBM, bn0 = blockIdx.x * GBN;
    const __half* Ab = A + (size_t)bm0 * K;
    const __half* Bb = B + (size_t)bn0 * K;

    auto load_stage = [&](int s, int kt) {
        uint32_t stg = sb + s * STG_BYTES;
#pragma unroll
        for (int j = 0; j < 6; j++) {
            int ci = tid + j * 256;
            uint32_t dst; const __half* src;
            if (ci < 512) {
                int r = ci >> 2, c = ci & 3;
                dst = stg + (uint32_t)(r * (GST*2) + c * 16);
                src = Ab + (size_t)r * K + kt * GBK + c * 8;
            } else {
                int li = ci - 512;
                int r = li >> 2, c = li & 3;
                dst = stg + A_BYTES + (uint32_t)(r * (GST*2) + c * 16);
                src = Bb + (size_t)r * K + kt * GBK + c * 8;
            }
            cp_async16(dst, src);
        }
        cp_commit();
    };

    float acc[4][8][4];
#pragma unroll
    for (int i = 0; i < 4; i++)
#pragma unroll
        for (int j = 0; j < 8; j++)
#pragma unroll
            for (int v = 0; v < 4; v++) acc[i][j][v] = 0.f;

    const int NIT = K / GBK;   // 128
    load_stage(0, 0);
    load_stage(1, 1);
    load_stage(2, 2);

    for (int it = 0; it < NIT; it++) {
        int s = it & 3;
        cp_wait<2>();
        __syncthreads();
        if (it + 3 < NIT) load_stage((it + 3) & 3, it + 3);
        else cp_commit();

        uint32_t As = sb + s * STG_BYTES;
        uint32_t Bs = As + A_BYTES;
#pragma unroll
        for (int kg = 0; kg < 2; kg++) {
            int kk = kg * 16;
            uint32_t af[4][4], bf[8][2];
#pragma unroll
            for (int mt = 0; mt < 4; mt++) {
                uint32_t row = (uint32_t)(wm * 64 + mt * 16 + (lane & 7) + ((lane >> 3) & 1) * 8);
                uint32_t col = (uint32_t)(kk + ((lane >> 4) & 1) * 8);
                ldsm_x4(af[mt], As + row * (GST*2) + col * 2);
            }
#pragma unroll
            for (int np = 0; np < 4; np++) {
                uint32_t row = (uint32_t)(wn * 64 + np * 16 + (lane & 7) + ((lane >> 4) & 1) * 8);
                uint32_t col = (uint32_t)(kk + ((lane >> 3) & 1) * 8);
                uint32_t t[4];
                ldsm_x4(t, Bs + row * (GST*2) + col * 2);
                bf[np*2][0] = t[0]; bf[np*2][1] = t[1];
                bf[np*2+1][0] = t[2]; bf[np*2+1][1] = t[3];
            }
#pragma unroll
            for (int mt = 0; mt < 4; mt++)
#pragma unroll
                for (int nt = 0; nt < 8; nt++)
                    mma_f16(acc[mt][nt], af[mt], bf[nt]);
        }
    }

    // epilogue
#pragma unroll
    for (int mt = 0; mt < 4; mt++) {
        int r0 = bm0 + wm * 64 + mt * 16 + g;
#pragma unroll
        for (int nt = 0; nt < 8; nt++) {
            int c = bn0 + wn * 64 + nt * 8 + tig * 2;
            if (HALF_OUT) {
                __half2* C = (__half2*)Cout;
                C[((size_t)r0 * N + c) >> 1] =
                    __floats2half2_rn(acc[mt][nt][0], acc[mt][nt][1]);
                C[((size_t)(r0 + 8) * N + c) >> 1] =
                    __floats2half2_rn(acc[mt][nt][2], acc[mt][nt][3]);
            } else {
                float* C = (float*)Cout;
                *(float2*)&C[(size_t)r0 * N + c] = make_float2(acc[mt][nt][0], acc[mt][nt][1]);
                *(float2*)&C[(size_t)(r0 + 8) * N + c] = make_float2(acc[mt][nt][2], acc[mt][nt][3]);
            }
        }
    }
}

// ============== fp16 flash attention v2: GQA KV-sharing ==============
// CTA: 64 seq positions x 4 q-heads (one kv group) = 256 q rows, 8 warps.
// Warp w: head_local = w>>1, positions (w&1)*32 .. +31, split into 2x16-row subtiles.
// K/V tiles of 64 keys, double-buffered cp.async; P stays in registers.
#define FQS 136
#define FKVT (64*FQS)                  // halves per KV tile
#define FQT  (256*FQS)                 // halves for Q
#define FLASH_SMEM ((FQT + 4*FKVT)*2)  // 139264 B

__global__ __launch_bounds__(256)
void flash2(const __half* __restrict__ QKV, __half* __restrict__ O) {
    extern __shared__ char fsm[];
    const uint32_t sb = smem_u32(fsm);
    const uint32_t KsA[2] = {sb,            sb + 2*FKVT*2};
    const uint32_t VsA[2] = {sb + FKVT*2,   sb + 3*FKVT*2};
    const uint32_t QsA    =  sb + 4*FKVT*2;

    const int tid = threadIdx.x;
    const int w = tid >> 5, lane = tid & 31;
    const int g = lane >> 2, tig = lane & 3;
    const int qb  = blockIdx.x;                  // 0..31 (position tile)
    const int bk  = blockIdx.y;                  // 0..15
    const int b   = bk >> 3;
    const int kvh = bk & 7;
    const int qm0 = qb * 64;
    const int hq  = w >> 1;                      // head_local 0..3
    const int prow = (w & 1) * 32;               // position base within tile

    const __half* base = QKV + (size_t)b * SEQ * QKVW;
    const __half* Kb = base + HID        + kvh * 128;
    const __half* Vb = base + HID + KVD  + kvh * 128;

    // ---- Q load: 256 rows (4 heads x 64 pos) x 128 halves = 4096 16B chunks ----
#pragma unroll
    for (int j = 0; j < 16; j++) {
        int ci = tid + j * 256;
        int r = ci >> 4, c = ci & 15;
        int hl = r >> 6, p = r & 63;
        cp_async16(QsA + (uint32_t)(r * (FQS*2) + c * 16),
                   base + (size_t)(qm0 + p) * QKVW + (kvh * 4 + hl) * 128 + c * 8);
    }
    cp_commit();

    auto load_kv = [&](int s, int kt) {
#pragma unroll
        for (int j = 0; j < 8; j++) {
            int ci = tid + j * 256;
            bool isK = ci < 1024;
            int li = isK ? ci : ci - 1024;
            int r = li >> 4, c = li & 15;
            uint32_t dst = (isK ? KsA[s] : VsA[s]) + (uint32_t)(r * (FQS*2) + c * 16);
            const __half* src = (isK ? Kb : Vb) + (size_t)(kt * 64 + r) * QKVW + c * 8;
            cp_async16(dst, src);
        }
        cp_commit();
    };

    load_kv(0, 0);

    float oacc[2][16][4];
#pragma unroll
    for (int s2 = 0; s2 < 2; s2++)
#pragma unroll
        for (int i = 0; i < 16; i++)
#pragma unroll
            for (int v = 0; v < 4; v++) oacc[s2][i][v] = 0.f;
    float mm[2][2] = {{-1e30f, -1e30f}, {-1e30f, -1e30f}};
    float ll[2][2] = {{0.f, 0.f}, {0.f, 0.f}};
    const float scale = 0.08838834764831845f;  // 1/sqrt(128)

    for (int kj = 0; kj <= qb; kj++) {
        const int bf = kj & 1;
        if (kj < qb) load_kv(bf ^ 1, kj + 1);
        else cp_commit();
        cp_wait<1>();
        __syncthreads();

#pragma unroll
        for (int sub = 0; sub < 2; sub++) {
            // Q fragments for this 16-row subtile
            uint32_t qf[8][4];
#pragma unroll
            for (int kg = 0; kg < 8; kg++) {
                uint32_t row = (uint32_t)(w * 32 + sub * 16 + (lane & 7) + ((lane >> 3) & 1) * 8);
                uint32_t col = (uint32_t)(kg * 16 + ((lane >> 4) & 1) * 8);
                ldsm_x4(qf[kg], QsA + row * (FQS*2) + col * 2);
            }

            // ---- S = Q K^T ----
            float sacc[8][4];
#pragma unroll
            for (int nt = 0; nt < 8; nt++)
#pragma unroll
                for (int v = 0; v < 4; v++) sacc[nt][v] = 0.f;

#pragma unroll
            for (int kg = 0; kg < 8; kg++) {
                uint32_t kf[8][2];
#pragma unroll
                for (int np = 0; np < 4; np++) {
                    uint32_t row = (uint32_t)(np * 16 + (lane & 7) + ((lane >> 4) & 1) * 8);
                    uint32_t col = (uint32_t)(kg * 16 + ((lane >> 3) & 1) * 8);
                    uint32_t t[4];
                    ldsm_x4(t, KsA[bf] + row * (FQS*2) + col * 2);
                    kf[np*2][0] = t[0]; kf[np*2][1] = t[1];
                    kf[np*2+1][0] = t[2]; kf[np*2+1][1] = t[3];
                }
#pragma unroll
                for (int nt = 0; nt < 8; nt++)
                    mma_f16(sacc[nt], qf[kg], kf[nt]);
            }

            // ---- scale + causal mask ----
#pragma unroll
            for (int nt = 0; nt < 8; nt++)
#pragma unroll
                for (int v = 0; v < 4; v++) sacc[nt][v] *= scale;

            const int q0 = qm0 + prow + sub * 16 + g;
            const int q1 = q0 + 8;
            if (kj == qb) {
#pragma unroll
                for (int nt = 0; nt < 8; nt++) {
                    int k0 = kj * 64 + nt * 8 + tig * 2;
                    if (k0     > q0) sacc[nt][0] = -1e30f;
                    if (k0 + 1 > q0) sacc[nt][1] = -1e30f;
                    if (k0     > q1) sacc[nt][2] = -1e30f;
                    if (k0 + 1 > q1) sacc[nt][3] = -1e30f;
                }
            }

            // ---- online softmax ----
            float rm0 = -1e30f, rm1 = -1e30f;
#pragma unroll
            for (int nt = 0; nt < 8; nt++) {
                rm0 = fmaxf(rm0, fmaxf(sacc[nt][0], sacc[nt][1]));
                rm1 = fmaxf(rm1, fmaxf(sacc[nt][2], sacc[nt][3]));
            }
            rm0 = fmaxf(rm0, __shfl_xor_sync(0xffffffffu, rm0, 1));
            rm0 = fmaxf(rm0, __shfl_xor_sync(0xffffffffu, rm0, 2));
            rm1 = fmaxf(rm1, __shfl_xor_sync(0xffffffffu, rm1, 1));
            rm1 = fmaxf(rm1, __shfl_xor_sync(0xffffffffu, rm1, 2));

            float mn0 = fmaxf(mm[sub][0], rm0), mn1 = fmaxf(mm[sub][1], rm1);
            float a0 = __expf(mm[sub][0] - mn0), a1 = __expf(mm[sub][1] - mn1);
            float rs0 = 0.f, rs1 = 0.f;
#pragma unroll
            for (int nt = 0; nt < 8; nt++) {
                sacc[nt][0] = __expf(sacc[nt][0] - mn0); rs0 += sacc[nt][0];
                sacc[nt][1] = __expf(sacc[nt][1] - mn0); rs0 += sacc[nt][1];
                sacc[nt][2] = __expf(sacc[nt][2] - mn1); rs1 += sacc[nt][2];
                sacc[nt][3] = __expf(sacc[nt][3] - mn1); rs1 += sacc[nt][3];
            }
            rs0 += __shfl_xor_sync(0xffffffffu, rs0, 1);
            rs0 += __shfl_xor_sync(0xffffffffu, rs0, 2);
            rs1 += __shfl_xor_sync(0xffffffffu, rs1, 1);
            rs1 += __shfl_xor_sync(0xffffffffu, rs1, 2);

            ll[sub][0] = ll[sub][0] * a0 + rs0;
            ll[sub][1] = ll[sub][1] * a1 + rs1;
            mm[sub][0] = mn0; mm[sub][1] = mn1;

#pragma unroll
            for (int nt = 0; nt < 16; nt++) {
                oacc[sub][nt][0] *= a0; oacc[sub][nt][1] *= a0;
                oacc[sub][nt][2] *= a1; oacc[sub][nt][3] *= a1;
            }

            // ---- P -> fp16 regs ----
            uint32_t pf[8][2];
#pragma unroll
            for (int nt = 0; nt < 8; nt++) {
                pf[nt][0] = pack_h2(sacc[nt][0], sacc[nt][1]);
                pf[nt][1] = pack_h2(sacc[nt][2], sacc[nt][3]);
            }

            // ---- O += P @ V ----
#pragma unroll
            for (int kg = 0; kg < 4; kg++) {
                uint32_t pa[4] = { pf[2*kg][0], pf[2*kg][1], pf[2*kg+1][0], pf[2*kg+1][1] };
#pragma unroll
                for (int dp = 0; dp < 8; dp++) {
                    uint32_t row = (uint32_t)(kg * 16 + (lane & 7) + ((lane >> 3) & 1) * 8);
                    uint32_t col = (uint32_t)(dp * 16 + ((lane >> 4) & 1) * 8);
                    uint32_t t[4];
                    ldsm_x4t(t, VsA[bf] + row * (FQS*2) + col * 2);
                    uint32_t b0[2] = { t[0], t[1] };
                    uint32_t b1[2] = { t[2], t[3] };
                    mma_f16(oacc[sub][dp*2],   pa, b0);
                    mma_f16(oacc[sub][dp*2+1], pa, b1);
                }
            }
        }
        __syncthreads();   // all warps done with buffer bf before refill
    }

    // ---- normalize + store fp16 O [MTOT, HID] ----
#pragma unroll
    for (int sub = 0; sub < 2; sub++) {
        float il0 = 1.f / ll[sub][0], il1 = 1.f / ll[sub][1];
        size_t ro0 = ((size_t)(b * SEQ + qm0 + prow + sub * 16 + g)) * HID
                   + (size_t)(kvh * 4 + hq) * 128;
        size_t ro1 = ro0 + (size_t)8 * HID;
#pragma unroll
        for (int nt = 0; nt < 16; nt++) {
            int c = nt * 8 + tig * 2;
            *(__half2*)&O[ro0 + c] = __floats2half2_rn(oacc[sub][nt][0] * il0, oacc[sub][nt][1] * il0);
            *(__half2*)&O[ro1 + c] = __floats2half2_rn(oacc[sub][nt][2] * il1, oacc[sub][nt][3] * il1);
        }
    }
}

// ---------------- launch ----------------
extern "C" void kernel_launch(void* const* d_in, const int* in_sizes, int n_in,
                              void* d_out, int out_size) {
    const float* hidden = (const float*)d_in[0];
    const int*   pos    = (const int*)d_in[1];
    const float* Wq     = (const float*)d_in[2];
    const float* Wk     = (const float*)d_in[3];
    const float* Wv     = (const float*)d_in[4];
    const float* Wo     = (const float*)d_in[5];
    float* out = (float*)d_out;

    __half *pAh, *pWh, *pWoh, *pQKV, *pOh;
    float *pc, *ps;
    cudaGetSymbolAddress((void**)&pAh,  g_Ah);
    cudaGetSymbolAddress((void**)&pWh,  g_Wh);
    cudaGetSymbolAddress((void**)&pWoh, g_Woh);
    cudaGetSymbolAddress((void**)&pQKV, g_QKVh);
    cudaGetSymbolAddress((void**)&pOh,  g_Oh);
    cudaGetSymbolAddress((void**)&pc,   g_cos);
    cudaGetSymbolAddress((void**)&ps,   g_sin);

    cudaFuncSetAttribute(gemm_h<true>,
                         cudaFuncAttributeMaxDynamicSharedMemorySize, GEMM_SMEM);
    cudaFuncSetAttribute(gemm_h<false>,
                         cudaFuncAttributeMaxDynamicSharedMemorySize, GEMM_SMEM);
    cudaFuncSetAttribute(flash2,
                         cudaFuncAttributeMaxDynamicSharedMemorySize, FLASH_SMEM);

    // RoPE tables
    rope_table_kernel<<<SEQ, 64>>>(pos, pc, ps);

    // fp32 -> fp16 converts (weights packed Wq|Wk|Wv)
    {
        int n8;
        n8 = (MTOT * HID) / 8;
        f2h_kernel<<<CDIV(n8, 256), 256>>>((const float4*)hidden, (uint4*)pAh, n8);
        n8 = (HID * HID) / 8;
        f2h_kernel<<<CDIV(n8, 256), 256>>>((const float4*)Wq, (uint4*)pWh, n8);
        f2h_kernel<<<CDIV(n8, 256), 256>>>((const float4*)Wo, (uint4*)pWoh, n8);
        n8 = (KVD * HID) / 8;
        f2h_kernel<<<CDIV(n8, 256), 256>>>((const float4*)Wk,
                                           (uint4*)(pWh + (size_t)HID * HID), n8);
        f2h_kernel<<<CDIV(n8, 256), 256>>>((const float4*)Wv,
                                           (uint4*)(pWh + (size_t)(HID + KVD) * HID), n8);
    }

    // fused QKV projection: [4096, 4096] x [6144, 4096]^T -> [4096, 6144]
    dim3 gqkv(QKVW / GBN, MTOT / GBM);       // (24, 32) = 768 blocks
    gemm_h<true><<<gqkv, 256, GEMM_SMEM>>>(pAh, pWh, pQKV, QKVW, HID);

    // RoPE on packed buffer (Q cols 0.., K cols HID..)
    int tq = MTOT * NH * 64;
    int tk = MTOT * KVH * 64;
    rope_qkv_kernel<<<CDIV(tq, 256), 256>>>(pQKV, pc, ps, NH, 0, tq);
    rope_qkv_kernel<<<CDIV(tk, 256), 256>>>(pQKV, pc, ps, KVH, HID, tk);

    // attention (GQA KV-sharing)
    dim3 gf(SEQ / 64, BATCH * KVH);          // (32, 16) = 512 blocks
    flash2<<<gf, 256, FLASH_SMEM>>>(pQKV, pOh);

    // output projection -> fp32 d_out
    dim3 go(HID / GBN, MTOT / GBM);          // (16, 32) = 512 blocks
    gemm_h<false><<<go, 256, GEMM_SMEM>>>(pOh, pWoh, out, HID, HID);
}

// round 10
// speedup vs baseline: 1.0033x; 1.0033x over previous
#include <cuda_runtime.h>
#include <cuda_fp16.h>
#include <cstdint>
#include <cstddef>

#define BATCH 2
#define SEQ   2048
#define HID   4096
#define NH    32
#define KVH   8
#define HD    128
#define MTOT  (BATCH*SEQ)      // 4096
#define KVD   (KVH*HD)         // 1024
#define QKVW  (HID + 2*KVD)    // 6144 packed width

#define CDIV(a,b) (((a)+(b)-1)/(b))

// ---------------- scratch (allocation-free: __device__ globals) ----------------
__device__ __half g_Ah  [MTOT*HID];        // fp16(hidden)
__device__ __half g_Wh  [QKVW*HID];        // packed Wq|Wk|Wv
__device__ __half g_Woh [HID*HID];
__device__ __half g_QKVh[MTOT*QKVW];       // packed Q|K|V
__device__ __half g_Oh  [MTOT*HID];
__device__ float  g_cos[SEQ*64];
__device__ float  g_sin[SEQ*64];

// ---------------- helpers ----------------
static __device__ __forceinline__ uint32_t smem_u32(const void* p) {
    uint32_t a;
    asm("{ .reg .u64 t; cvta.to.shared.u64 t, %1; cvt.u32.u64 %0, t; }" : "=r"(a) : "l"(p));
    return a;
}

static __device__ __forceinline__ void mma_f16(float* d, const uint32_t* a, const uint32_t* b) {
    asm volatile(
        "mma.sync.aligned.m16n8k16.row.col.f32.f16.f16.f32 "
        "{%0,%1,%2,%3}, {%4,%5,%6,%7}, {%8,%9}, {%0,%1,%2,%3};\n"
        : "+f"(d[0]), "+f"(d[1]), "+f"(d[2]), "+f"(d[3])
        : "r"(a[0]), "r"(a[1]), "r"(a[2]), "r"(a[3]),
          "r"(b[0]), "r"(b[1]));
}

static __device__ __forceinline__ void ldsm_x4(uint32_t* r, uint32_t addr) {
    asm volatile("ldmatrix.sync.aligned.m8n8.x4.shared.b16 {%0,%1,%2,%3}, [%4];"
                 : "=r"(r[0]), "=r"(r[1]), "=r"(r[2]), "=r"(r[3]) : "r"(addr));
}
static __device__ __forceinline__ void ldsm_x4t(uint32_t* r, uint32_t addr) {
    asm volatile("ldmatrix.sync.aligned.m8n8.x4.trans.shared.b16 {%0,%1,%2,%3}, [%4];"
                 : "=r"(r[0]), "=r"(r[1]), "=r"(r[2]), "=r"(r[3]) : "r"(addr));
}

static __device__ __forceinline__ void cp_async16(uint32_t dst, const void* src) {
    asm volatile("cp.async.cg.shared.global [%0], [%1], 16;" :: "r"(dst), "l"(src));
}
static __device__ __forceinline__ void cp_commit() {
    asm volatile("cp.async.commit_group;" ::: "memory");
}
template<int N> static __device__ __forceinline__ void cp_wait() {
    asm volatile("cp.async.wait_group %0;" :: "n"(N) : "memory");
}

static __device__ __forceinline__ uint32_t pack_h2(float a, float b) {
    __half2 h = __floats2half2_rn(a, b);
    return *reinterpret_cast<uint32_t*>(&h);
}

// ---------------- fp32 -> fp16 convert (8 elts/thread) ----------------
__global__ void f2h_kernel(const float4* __restrict__ in, uint4* __restrict__ out, int n8) {
    int i = blockIdx.x * blockDim.x + threadIdx.x;
    if (i >= n8) return;
    float4 a = in[2*i], b = in[2*i+1];
    uint4 o;
    o.x = pack_h2(a.x, a.y); o.y = pack_h2(a.z, a.w);
    o.z = pack_h2(b.x, b.y); o.w = pack_h2(b.z, b.w);
    out[i] = o;
}

// ---------------- RoPE ----------------
__global__ void rope_table_kernel(const int* __restrict__ pos,
                                  float* __restrict__ ct, float* __restrict__ st) {
    int s = blockIdx.x;
    int i = threadIdx.x;             // 0..63
    double inv = exp(-9.210340371976184 * (double)i / 64.0);  // 10000^(-2i/128)
    double ang = (double)pos[s] * inv;
    ct[s*64 + i] = (float)cos(ang);
    st[s*64 + i] = (float)sin(ang);
}

// RoPE on packed QKV buffer [MTOT, QKVW]; colbase selects Q (0) or K (HID) region
__global__ void rope_qkv_kernel(__half* __restrict__ X, const float* __restrict__ ct,
                                const float* __restrict__ st, int nh, int colbase, int total) {
    int idx = blockIdx.x * blockDim.x + threadIdx.x;
    if (idx >= total) return;
    int i   = idx & 63;
    int h   = (idx >> 6) % nh;
    int row = idx / (64 * nh);        // b*SEQ + s
    int s   = row & (SEQ - 1);
    float c  = ct[s*64 + i];
    float sn = st[s*64 + i];
    size_t base = (size_t)row * QKVW + colbase + h * 128 + i;
    float x1 = __half2float(X[base]);
    float x2 = __half2float(X[base + 64]);
    X[base]      = __float2half_rn(x1 * c - x2 * sn);
    X[base + 64] = __float2half_rn(x2 * c + x1 * sn);
}

// ============== fp16 tensor-core GEMM: C[M,N] = A[M,K] * B[N,K]^T ==============
// CTA 128x256, 8 warps (2x4) of 64x64, BK=32, 4-stage cp.async,
// explicit kg0/kg1 fragment double-buffer (all 16 LDSM issued before mmas).
#define GBM 128
#define GBN 256
#define GBK 32
#define GSTG 4
#define GST 40                               // halves per row (32 + 8 pad)
#define A_BYTES (GBM*GST*2)                  // 10240
#define B_BYTES (GBN*GST*2)                  // 20480
#define STG_BYTES (A_BYTES + B_BYTES)        // 30720
#define GEMM_SMEM (GSTG*STG_BYTES)           // 122880

template<bool HALF_OUT>
__global__ __launch_bounds__(256, 1)
void gemm_h(const __half* __restrict__ A, const __half* __restrict__ B,
            void* __restrict__ Cout, int N, int K) {
    extern __shared__ char smem[];
    const uint32_t sb = smem_u32(smem);
    const int tid = threadIdx.x, lane = tid & 31, warp = tid >> 5;
    const int wm = warp >> 2, wn = warp & 3;          // 2 x 4
    const int g = lane >> 2, tig = lane & 3;
    const int bm0 = blockIdx.y * GBM, bn0 = blockIdx.x * GBN;
    const __half* Ab = A + (size_t)bm0 * K;
    const __half* Bb = B + (size_t)bn0 * K;

    auto load_stage = [&](int s, int kt) {
        uint32_t stg = sb + s * STG_BYTES;
#pragma unroll
        for (int j = 0; j < 6; j++) {
            int ci = tid + j * 256;
            uint32_t dst; const __half* src;
            if (ci < 512) {
                int r = ci >> 2, c = ci & 3;
                dst = stg + (uint32_t)(r * (GST*2) + c * 16);
                src = Ab + (size_t)r * K + kt * GBK + c * 8;
            } else {
                int li = ci - 512;
                int r = li >> 2, c = li & 3;
                dst = stg + A_BYTES + (uint32_t)(r * (GST*2) + c * 16);
                src = Bb + (size_t)r * K + kt * GBK + c * 8;
            }
            cp_async16(dst, src);
        }
        cp_commit();
    };

    float acc[4][8][4];
#pragma unroll
    for (int i = 0; i < 4; i++)
#pragma unroll
        for (int j = 0; j < 8; j++)
#pragma unroll
            for (int v = 0; v < 4; v++) acc[i][j][v] = 0.f;

    // precomputed intra-stage LDSM offsets
    uint32_t a_off[2], b_off[2];
#pragma unroll
    for (int kg = 0; kg < 2; kg++) {
        uint32_t arow = (uint32_t)(wm * 64 + (lane & 7) + ((lane >> 3) & 1) * 8);
        uint32_t acol = (uint32_t)(kg * 16 + ((lane >> 4) & 1) * 8);
        a_off[kg] = arow * (GST*2) + acol * 2;
        uint32_t brow = (uint32_t)(wn * 64 + (lane & 7) + ((lane >> 4) & 1) * 8);
        uint32_t bcol = (uint32_t)(kg * 16 + ((lane >> 3) & 1) * 8);
        b_off[kg] = brow * (GST*2) + bcol * 2;
    }

    const int NIT = K / GBK;   // K/32
    load_stage(0, 0);
    load_stage(1, 1);
    load_stage(2, 2);

    for (int it = 0; it < NIT; it++) {
        int s = it & 3;
        cp_wait<2>();
        __syncthreads();
        if (it + 3 < NIT) load_stage((it + 3) & 3, it + 3);
        else cp_commit();

        uint32_t As = sb + s * STG_BYTES;
        uint32_t Bs = As + A_BYTES;

        // issue ALL fragment loads for both k-groups first (latency overlap)
        uint32_t af[2][4][4], bf[2][8][2];
#pragma unroll
        for (int kg = 0; kg < 2; kg++) {
#pragma unroll
            for (int mt = 0; mt < 4; mt++)
                ldsm_x4(af[kg][mt], As + a_off[kg] + (uint32_t)(mt * 16 * (GST*2)));
#pragma unroll
            for (int np = 0; np < 4; np++) {
                uint32_t t[4];
                ldsm_x4(t, Bs + b_off[kg] + (uint32_t)(np * 16 * (GST*2)));
                bf[kg][np*2][0] = t[0]; bf[kg][np*2][1] = t[1];
                bf[kg][np*2+1][0] = t[2]; bf[kg][np*2+1][1] = t[3];
            }
        }
#pragma unroll
        for (int kg = 0; kg < 2; kg++)
#pragma unroll
            for (int mt = 0; mt < 4; mt++)
#pragma unroll
                for (int nt = 0; nt < 8; nt++)
                    mma_f16(acc[mt][nt], af[kg][mt], bf[kg][nt]);
    }

    // epilogue
#pragma unroll
    for (int mt = 0; mt < 4; mt++) {
        int r0 = bm0 + wm * 64 + mt * 16 + g;
#pragma unroll
        for (int nt = 0; nt < 8; nt++) {
            int c = bn0 + wn * 64 + nt * 8 + tig * 2;
            if (HALF_OUT) {
                __half2* C = (__half2*)Cout;
                C[((size_t)r0 * N + c) >> 1] =
                    __floats2half2_rn(acc[mt][nt][0], acc[mt][nt][1]);
                C[((size_t)(r0 + 8) * N + c) >> 1] =
                    __floats2half2_rn(acc[mt][nt][2], acc[mt][nt][3]);
            } else {
                float* C = (float*)Cout;
                *(float2*)&C[(size_t)r0 * N + c] = make_float2(acc[mt][nt][0], acc[mt][nt][1]);
                *(float2*)&C[(size_t)(r0 + 8) * N + c] = make_float2(acc[mt][nt][2], acc[mt][nt][3]);
            }
        }
    }
}

// ============== fp16 flash attention (causal, GQA), Q-persistent ==============
// 4 warps, 64 q rows (16/warp), kv tiles of 64, D=128. P stays in registers.
// Reads packed QKV [MTOT, QKVW]; smem: K0,V0,K1,V1 (double-buffered), Q.
#define FQS 136
#define FTILE (64*FQS)                 // halves
#define FLASH_SMEM (FTILE*5*2)         // 87040 B

__global__ __launch_bounds__(128, 1)
void flash_h(const __half* __restrict__ QKV, __half* __restrict__ O) {
    extern __shared__ char fsm[];
    const uint32_t sb = smem_u32(fsm);
    const uint32_t KsA[2] = {sb,              sb + 2*FTILE*2};
    const uint32_t VsA[2] = {sb + FTILE*2,    sb + 3*FTILE*2};
    const uint32_t QsA    =  sb + 4*FTILE*2;

    const int tid = threadIdx.x;
    const int w = tid >> 5, lane = tid & 31;
    const int g = lane >> 2, tig = lane & 3;
    const int qb  = blockIdx.x;               // 0..31
    const int bh  = blockIdx.y;               // 0..63
    const int b   = bh >> 5;
    const int h   = bh & 31;
    const int kvh = h >> 2;                   // GROUPS=4 consecutive
    const int qm0 = qb * 64;

    const __half* base = QKV + (size_t)b * SEQ * QKVW;
    const __half* Qb = base + h * 128;
    const __half* Kb = base + HID + kvh * 128;
    const __half* Vb = base + HID + KVD + kvh * 128;

    // Q tile: 64 rows x 128 halves = 1024 chunks
#pragma unroll
    for (int j = 0; j < 8; j++) {
        int ci = tid + j * 128;
        int r = ci >> 4, c = ci & 15;
        cp_async16(QsA + (uint32_t)(r * (FQS*2) + c * 16),
                   Qb + (size_t)(qm0 + r) * QKVW + c * 8);
    }
    cp_commit();

    auto load_kv = [&](int s, int kt) {
#pragma unroll
        for (int j = 0; j < 16; j++) {
            int ci = tid + j * 128;
            bool isK = ci < 1024;
            int li = isK ? ci : ci - 1024;
            int r = li >> 4, c = li & 15;
            uint32_t dst = (isK ? KsA[s] : VsA[s]) + (uint32_t)(r * (FQS*2) + c * 16);
            const __half* src = (isK ? Kb : Vb) + (size_t)(kt * 64 + r) * QKVW + c * 8;
            cp_async16(dst, src);
        }
        cp_commit();
    };

    load_kv(0, 0);

    cp_wait<1>();            // Q loaded (KV0 may still be in flight)
    __syncthreads();

    // Q fragments (this warp's 16 rows), persistent across the K-loop
    uint32_t qf[8][4];
#pragma unroll
    for (int kg = 0; kg < 8; kg++) {
        uint32_t row = (uint32_t)(w * 16 + (lane & 7) + ((lane >> 3) & 1) * 8);
        uint32_t col = (uint32_t)(kg * 16 + ((lane >> 4) & 1) * 8);
        ldsm_x4(qf[kg], QsA + row * (FQS*2) + col * 2);
    }

    float oacc[16][4];
#pragma unroll
    for (int i = 0; i < 16; i++)
#pragma unroll
        for (int v = 0; v < 4; v++) oacc[i][v] = 0.f;
    float m0 = -1e30f, m1 = -1e30f, l0 = 0.f, l1 = 0.f;
    const float scale = 0.08838834764831845f;  // 1/sqrt(128)

    for (int kj = 0; kj <= qb; kj++) {
        const int bf = kj & 1;
        if (kj < qb) load_kv(bf ^ 1, kj + 1);
        else cp_commit();
        cp_wait<1>();         // current tile's loads complete
        __syncthreads();

        // ---- S = Q K^T ----
        float sacc[8][4];
#pragma unroll
        for (int nt = 0; nt < 8; nt++)
#pragma unroll
            for (int v = 0; v < 4; v++) sacc[nt][v] = 0.f;

#pragma unroll
        for (int kg = 0; kg < 8; kg++) {
            uint32_t kf[8][2];
#pragma unroll
            for (int np = 0; np < 4; np++) {
                uint32_t row = (uint32_t)(np * 16 + (lane & 7) + ((lane >> 4) & 1) * 8);
                uint32_t col = (uint32_t)(kg * 16 + ((lane >> 3) & 1) * 8);
                uint32_t t[4];
                ldsm_x4(t, KsA[bf] + row * (FQS*2) + col * 2);
                kf[np*2][0] = t[0]; kf[np*2][1] = t[1];
                kf[np*2+1][0] = t[2]; kf[np*2+1][1] = t[3];
            }
#pragma unroll
            for (int nt = 0; nt < 8; nt++)
                mma_f16(sacc[nt], qf[kg], kf[nt]);
        }

        // ---- scale + causal mask ----
#pragma unroll
        for (int nt = 0; nt < 8; nt++)
#pragma unroll
            for (int v = 0; v < 4; v++) sacc[nt][v] *= scale;

        const int q0 = qm0 + w * 16 + g;
        const int q1 = q0 + 8;
        if (kj == qb) {
#pragma unroll
            for (int nt = 0; nt < 8; nt++) {
                int k0 = kj * 64 + nt * 8 + tig * 2;
                if (k0     > q0) sacc[nt][0] = -1e30f;
                if (k0 + 1 > q0) sacc[nt][1] = -1e30f;
                if (k0     > q1) sacc[nt][2] = -1e30f;
                if (k0 + 1 > q1) sacc[nt][3] = -1e30f;
            }
        }

        // ---- online softmax ----
        float rm0 = -1e30f, rm1 = -1e30f;
#pragma unroll
        for (int nt = 0; nt < 8; nt++) {
            rm0 = fmaxf(rm0, fmaxf(sacc[nt][0], sacc[nt][1]));
            rm1 = fmaxf(rm1, fmaxf(sacc[nt][2], sacc[nt][3]));
        }
        rm0 = fmaxf(rm0, __shfl_xor_sync(0xffffffffu, rm0, 1));
        rm0 = fmaxf(rm0, __shfl_xor_sync(0xffffffffu, rm0, 2));
        rm1 = fmaxf(rm1, __shfl_xor_sync(0xffffffffu, rm1, 1));
        rm1 = fmaxf(rm1, __shfl_xor_sync(0xffffffffu, rm1, 2));

        float mn0 = fmaxf(m0, rm0), mn1 = fmaxf(m1, rm1);
        float a0 = __expf(m0 - mn0), a1 = __expf(m1 - mn1);
        float rs0 = 0.f, rs1 = 0.f;
#pragma unroll
        for (int nt = 0; nt < 8; nt++) {
            sacc[nt][0] = __expf(sacc[nt][0] - mn0); rs0 += sacc[nt][0];
            sacc[nt][1] = __expf(sacc[nt][1] - mn0); rs0 += sacc[nt][1];
            sacc[nt][2] = __expf(sacc[nt][2] - mn1); rs1 += sacc[nt][2];
            sacc[nt][3] = __expf(sacc[nt][3] - mn1); rs1 += sacc[nt][3];
        }
        rs0 += __shfl_xor_sync(0xffffffffu, rs0, 1);
        rs0 += __shfl_xor_sync(0xffffffffu, rs0, 2);
        rs1 += __shfl_xor_sync(0xffffffffu, rs1, 1);
        rs1 += __shfl_xor_sync(0xffffffffu, rs1, 2);

        l0 = l0 * a0 + rs0;
        l1 = l1 * a1 + rs1;
        m0 = mn0; m1 = mn1;

#pragma unroll
        for (int nt = 0; nt < 16; nt++) {
            oacc[nt][0] *= a0; oacc[nt][1] *= a0;
            oacc[nt][2] *= a1; oacc[nt][3] *= a1;
        }

        // ---- P -> fp16 in registers ----
        uint32_t pf[8][2];
#pragma unroll
        for (int nt = 0; nt < 8; nt++) {
            pf[nt][0] = pack_h2(sacc[nt][0], sacc[nt][1]);   // row g
            pf[nt][1] = pack_h2(sacc[nt][2], sacc[nt][3]);   // row g+8
        }

        // ---- O += P @ V ----
#pragma unroll
        for (int kg = 0; kg < 4; kg++) {
            uint32_t pa[4] = { pf[2*kg][0], pf[2*kg][1], pf[2*kg+1][0], pf[2*kg+1][1] };
#pragma unroll
            for (int dp = 0; dp < 8; dp++) {
                uint32_t row = (uint32_t)(kg * 16 + (lane & 7) + ((lane >> 3) & 1) * 8);
                uint32_t col = (uint32_t)(dp * 16 + ((lane >> 4) & 1) * 8);
                uint32_t t[4];
                ldsm_x4t(t, VsA[bf] + row * (FQS*2) + col * 2);
                uint32_t b0[2] = { t[0], t[1] };
                uint32_t b1[2] = { t[2], t[3] };
                mma_f16(oacc[dp*2],   pa, b0);
                mma_f16(oacc[dp*2+1], pa, b1);
            }
        }
        __syncthreads();   // all warps done with buf before it is refilled
    }

    // ---- normalize + store fp16 O [MTOT, HID] ----
    float il0 = 1.f / l0, il1 = 1.f / l1;
    size_t ro0 = ((size_t)(b * SEQ + qm0 + w * 16 + g)) * HID + (size_t)h * 128;
    size_t ro1 = ro0 + (size_t)8 * HID;
#pragma unroll
    for (int nt = 0; nt < 16; nt++) {
        int c = nt * 8 + tig * 2;
        *(__half2*)&O[ro0 + c] = __floats2half2_rn(oacc[nt][0] * il0, oacc[nt][1] * il0);
        *(__half2*)&O[ro1 + c] = __floats2half2_rn(oacc[nt][2] * il1, oacc[nt][3] * il1);
    }
}

// ---------------- launch ----------------
extern "C" void kernel_launch(void* const* d_in, const int* in_sizes, int n_in,
                              void* d_out, int out_size) {
    const float* hidden = (const float*)d_in[0];
    const int*   pos    = (const int*)d_in[1];
    const float* Wq     = (const float*)d_in[2];
    const float* Wk     = (const float*)d_in[3];
    const float* Wv     = (const float*)d_in[4];
    const float* Wo     = (const float*)d_in[5];
    float* out = (float*)d_out;

    __half *pAh, *pWh, *pWoh, *pQKV, *pOh;
    float *pc, *ps;
    cudaGetSymbolAddress((void**)&pAh,  g_Ah);
    cudaGetSymbolAddress((void**)&pWh,  g_Wh);
    cudaGetSymbolAddress((void**)&pWoh, g_Woh);
    cudaGetSymbolAddress((void**)&pQKV, g_QKVh);
    cudaGetSymbolAddress((void**)&pOh,  g_Oh);
    cudaGetSymbolAddress((void**)&pc,   g_cos);
    cudaGetSymbolAddress((void**)&ps,   g_sin);

    cudaFuncSetAttribute(gemm_h<true>,
                         cudaFuncAttributeMaxDynamicSharedMemorySize, GEMM_SMEM);
    cudaFuncSetAttribute(gemm_h<false>,
                         cudaFuncAttributeMaxDynamicSharedMemorySize, GEMM_SMEM);
    cudaFuncSetAttribute(flash_h,
                         cudaFuncAttributeMaxDynamicSharedMemorySize, FLASH_SMEM);

    // launches 1-5: fp32 -> fp16 converts (weights packed Wq|Wk|Wv)
    {
        int n8;
        n8 = (HID * HID) / 8;
        f2h_kernel<<<CDIV(n8, 256), 256>>>((const float4*)Wq, (uint4*)pWh, n8);
        f2h_kernel<<<CDIV(n8, 256), 256>>>((const float4*)Wo, (uint4*)pWoh, n8);
        n8 = (KVD * HID) / 8;
        f2h_kernel<<<CDIV(n8, 256), 256>>>((const float4*)Wk,
                                           (uint4*)(pWh + (size_t)HID * HID), n8);
        f2h_kernel<<<CDIV(n8, 256), 256>>>((const float4*)Wv,
                                           (uint4*)(pWh + (size_t)(HID + KVD) * HID), n8);
        n8 = (MTOT * HID) / 8;
        f2h_kernel<<<CDIV(n8, 256), 256>>>((const float4*)hidden, (uint4*)pAh, n8);
    }

    // launch 6 (ncu -s 5 captures this): fused QKV projection
    dim3 gqkv(QKVW / GBN, MTOT / GBM);       // (24, 32) = 768 blocks
    gemm_h<true><<<gqkv, 256, GEMM_SMEM>>>(pAh, pWh, pQKV, QKVW, HID);

    // RoPE tables (independent of GEMM; only needs pos)
    rope_table_kernel<<<SEQ, 64>>>(pos, pc, ps);

    // RoPE on packed buffer (Q cols 0.., K cols HID..)
    int tq = MTOT * NH * 64;
    int tk = MTOT * KVH * 64;
    rope_qkv_kernel<<<CDIV(tq, 256), 256>>>(pQKV, pc, ps, NH, 0, tq);
    rope_qkv_kernel<<<CDIV(tk, 256), 256>>>(pQKV, pc, ps, KVH, HID, tk);

    // attention
    dim3 gf(SEQ / 64, BATCH * NH);           // (32, 64)
    flash_h<<<gf, 128, FLASH_SMEM>>>(pQKV, pOh);

    // output projection -> fp32 d_out
    dim3 go(HID / GBN, MTOT / GBM);          // (16, 32)
    gemm_h<false><<<go, 256, GEMM_SMEM>>>(pOh, pWoh, out, HID, HID);
}

// round 11
// speedup vs baseline: 1.0995x; 1.0959x over previous
#include <cuda_runtime.h>
#include <cuda_fp16.h>
#include <cstdint>
#include <cstddef>

#define BATCH 2
#define SEQ   2048
#define HID   4096
#define NH    32
#define KVH   8
#define HD    128
#define MTOT  (BATCH*SEQ)      // 4096
#define KVD   (KVH*HD)         // 1024
#define QKVW  (HID + 2*KVD)    // 6144 packed width

#define CDIV(a,b) (((a)+(b)-1)/(b))

// ---------------- scratch (allocation-free: __device__ globals) ----------------
__device__ __half g_Ah  [MTOT*HID];        // fp16(hidden)
__device__ __half g_Wh  [QKVW*HID];        // packed Wq|Wk|Wv
__device__ __half g_Woh [HID*HID];
__device__ __half g_QKVh[MTOT*QKVW];       // packed Q|K|V
__device__ __half g_Oh  [MTOT*HID];
__device__ float  g_cos[SEQ*64];
__device__ float  g_sin[SEQ*64];

// ---------------- helpers ----------------
static __device__ __forceinline__ uint32_t smem_u32(const void* p) {
    uint32_t a;
    asm("{ .reg .u64 t; cvta.to.shared.u64 t, %1; cvt.u32.u64 %0, t; }" : "=r"(a) : "l"(p));
    return a;
}

static __device__ __forceinline__ void mma_f16(float* d, const uint32_t* a, const uint32_t* b) {
    asm volatile(
        "mma.sync.aligned.m16n8k16.row.col.f32.f16.f16.f32 "
        "{%0,%1,%2,%3}, {%4,%5,%6,%7}, {%8,%9}, {%0,%1,%2,%3};\n"
        : "+f"(d[0]), "+f"(d[1]), "+f"(d[2]), "+f"(d[3])
        : "r"(a[0]), "r"(a[1]), "r"(a[2]), "r"(a[3]),
          "r"(b[0]), "r"(b[1]));
}

static __device__ __forceinline__ void ldsm_x4(uint32_t* r, uint32_t addr) {
    asm volatile("ldmatrix.sync.aligned.m8n8.x4.shared.b16 {%0,%1,%2,%3}, [%4];"
                 : "=r"(r[0]), "=r"(r[1]), "=r"(r[2]), "=r"(r[3]) : "r"(addr));
}
static __device__ __forceinline__ void ldsm_x4t(uint32_t* r, uint32_t addr) {
    asm volatile("ldmatrix.sync.aligned.m8n8.x4.trans.shared.b16 {%0,%1,%2,%3}, [%4];"
                 : "=r"(r[0]), "=r"(r[1]), "=r"(r[2]), "=r"(r[3]) : "r"(addr));
}

static __device__ __forceinline__ void cp_async16(uint32_t dst, const void* src) {
    asm volatile("cp.async.cg.shared.global [%0], [%1], 16;" :: "r"(dst), "l"(src));
}
static __device__ __forceinline__ void cp_commit() {
    asm volatile("cp.async.commit_group;" ::: "memory");
}
template<int N> static __device__ __forceinline__ void cp_wait() {
    asm volatile("cp.async.wait_group %0;" :: "n"(N) : "memory");
}

static __device__ __forceinline__ uint32_t pack_h2(float a, float b) {
    __half2 h = __floats2half2_rn(a, b);
    return *reinterpret_cast<uint32_t*>(&h);
}

// ---------------- fused fp32 -> fp16 convert over 5 regions ----------------
struct F2HArgs {
    const float4* src[5];
    uint4*        dst[5];
    int           cum[6];   // cumulative counts in uint4-of-half8 units
};

__global__ void f2h_all_kernel(F2HArgs a) {
    int i = blockIdx.x * blockDim.x + threadIdx.x;
    if (i >= a.cum[5]) return;
    int r = 0;
    if (i >= a.cum[3]) r = (i >= a.cum[4]) ? 4 : 3;
    else if (i >= a.cum[2]) r = 2;
    else if (i >= a.cum[1]) r = 1;
    int li = i - a.cum[r];
    float4 x = a.src[r][2*li], y = a.src[r][2*li+1];
    uint4 o;
    o.x = pack_h2(x.x, x.y); o.y = pack_h2(x.z, x.w);
    o.z = pack_h2(y.x, y.y); o.w = pack_h2(y.z, y.w);
    a.dst[r][li] = o;
}

// ---------------- RoPE ----------------
__global__ void rope_table_kernel(const int* __restrict__ pos,
                                  float* __restrict__ ct, float* __restrict__ st) {
    int s = blockIdx.x;
    int i = threadIdx.x;             // 0..63
    double inv = exp(-9.210340371976184 * (double)i / 64.0);  // 10000^(-2i/128)
    double ang = (double)pos[s] * inv;
    ct[s*64 + i] = (float)cos(ang);
    st[s*64 + i] = (float)sin(ang);
}

// RoPE on packed QKV buffer [MTOT, QKVW]; colbase selects Q (0) or K (HID) region
__global__ void rope_qkv_kernel(__half* __restrict__ X, const float* __restrict__ ct,
                                const float* __restrict__ st, int nh, int colbase, int total) {
    int idx = blockIdx.x * blockDim.x + threadIdx.x;
    if (idx >= total) return;
    int i   = idx & 63;
    int h   = (idx >> 6) % nh;
    int row = idx / (64 * nh);        // b*SEQ + s
    int s   = row & (SEQ - 1);
    float c  = ct[s*64 + i];
    float sn = st[s*64 + i];
    size_t base = (size_t)row * QKVW + colbase + h * 128 + i;
    float x1 = __half2float(X[base]);
    float x2 = __half2float(X[base + 64]);
    X[base]      = __float2half_rn(x1 * c - x2 * sn);
    X[base + 64] = __float2half_rn(x2 * c + x1 * sn);
}

// ============== fp16 tensor-core GEMM: C[M,N] = A[M,K] * B[N,K]^T ==============
// CTA 128x256, 8 warps (2x4) of 64x64, BK=64 per mainloop iter, 3-stage cp.async.
#define GBM 128
#define GBN 256
#define GBK 64
#define GSTG 3
#define GST 72                               // halves per row (64 + 8 pad)
#define A_BYTES (GBM*GST*2)                  // 18432
#define B_BYTES (GBN*GST*2)                  // 36864
#define STG_BYTES (A_BYTES + B_BYTES)        // 55296
#define GEMM_SMEM (GSTG*STG_BYTES)           // 165888

template<bool HALF_OUT>
__global__ __launch_bounds__(256, 1)
void gemm_h(const __half* __restrict__ A, const __half* __restrict__ B,
            void* __restrict__ Cout, int N, int K) {
    extern __shared__ char smem[];
    const uint32_t sb = smem_u32(smem);
    const int tid = threadIdx.x, lane = tid & 31, warp = tid >> 5;
    const int wm = warp >> 2, wn = warp & 3;          // 2 x 4
    const int g = lane >> 2, tig = lane & 3;
    const int bm0 = blockIdx.y * GBM, bn0 = blockIdx.x * GBN;
    const __half* Ab = A + (size_t)bm0 * K;
    const __half* Bb = B + (size_t)bn0 * K;

    // stage loader: A 1024 + B 2048 = 3072 16B chunks, 12 per thread
    auto load_stage = [&](int s, int kt) {
        uint32_t stg = sb + s * STG_BYTES;
#pragma unroll
        for (int j = 0; j < 12; j++) {
            int ci = tid + j * 256;
            uint32_t dst; const __half* src;
            if (ci < 1024) {
                int r = ci >> 3, c = ci & 7;
                dst = stg + (uint32_t)(r * (GST*2) + c * 16);
                src = Ab + (size_t)r * K + kt * GBK + c * 8;
            } else {
                int li = ci - 1024;
                int r = li >> 3, c = li & 7;
                dst = stg + A_BYTES + (uint32_t)(r * (GST*2) + c * 16);
                src = Bb + (size_t)r * K + kt * GBK + c * 8;
            }
            cp_async16(dst, src);
        }
        cp_commit();
    };

    float acc[4][8][4];
#pragma unroll
    for (int i = 0; i < 4; i++)
#pragma unroll
        for (int j = 0; j < 8; j++)
#pragma unroll
            for (int v = 0; v < 4; v++) acc[i][j][v] = 0.f;

    const uint32_t a_base = (uint32_t)((wm * 64 + (lane & 7) + ((lane >> 3) & 1) * 8) * (GST*2)
                                       + (((lane >> 4) & 1) * 8) * 2);
    const uint32_t b_base = (uint32_t)((wn * 64 + (lane & 7) + ((lane >> 4) & 1) * 8) * (GST*2)
                                       + (((lane >> 3) & 1) * 8) * 2);

    const int NIT = K / GBK;   // K/64
    load_stage(0, 0);
    load_stage(1, 1);

    for (int it = 0; it < NIT; it++) {
        int s = it % 3;
        cp_wait<1>();
        __syncthreads();
        if (it + 2 < NIT) load_stage((it + 2) % 3, it + 2);
        else cp_commit();

        uint32_t As = sb + s * STG_BYTES;
        uint32_t Bs = As + A_BYTES;

#pragma unroll
        for (int kg = 0; kg < 4; kg++) {
            uint32_t kcol = (uint32_t)(kg * 16 * 2);
            uint32_t af[4][4], bf[8][2];
#pragma unroll
            for (int mt = 0; mt < 4; mt++)
                ldsm_x4(af[mt], As + a_base + kcol + (uint32_t)(mt * 16 * (GST*2)));
#pragma unroll
            for (int np = 0; np < 4; np++) {
                uint32_t t[4];
                ldsm_x4(t, Bs + b_base + kcol + (uint32_t)(np * 16 * (GST*2)));
                bf[np*2][0] = t[0]; bf[np*2][1] = t[1];
                bf[np*2+1][0] = t[2]; bf[np*2+1][1] = t[3];
            }
#pragma unroll
            for (int mt = 0; mt < 4; mt++)
#pragma unroll
                for (int nt = 0; nt < 8; nt++)
                    mma_f16(acc[mt][nt], af[mt], bf[nt]);
        }
    }

    // epilogue
#pragma unroll
    for (int mt = 0; mt < 4; mt++) {
        int r0 = bm0 + wm * 64 + mt * 16 + g;
#pragma unroll
        for (int nt = 0; nt < 8; nt++) {
            int c = bn0 + wn * 64 + nt * 8 + tig * 2;
            if (HALF_OUT) {
                __half2* C = (__half2*)Cout;
                C[((size_t)r0 * N + c) >> 1] =
                    __floats2half2_rn(acc[mt][nt][0], acc[mt][nt][1]);
                C[((size_t)(r0 + 8) * N + c) >> 1] =
                    __floats2half2_rn(acc[mt][nt][2], acc[mt][nt][3]);
            } else {
                float* C = (float*)Cout;
                *(float2*)&C[(size_t)r0 * N + c] = make_float2(acc[mt][nt][0], acc[mt][nt][1]);
                *(float2*)&C[(size_t)(r0 + 8) * N + c] = make_float2(acc[mt][nt][2], acc[mt][nt][3]);
            }
        }
    }
}

// ============== fp16 flash attention (causal, GQA), Q-persistent ==============
// 4 warps, 64 q rows (16/warp), kv tiles of 64, D=128. P stays in registers.
// Reads packed QKV [MTOT, QKVW]; smem: K0,V0,K1,V1 (double-buffered), Q.
#define FQS 136
#define FTILE (64*FQS)                 // halves
#define FLASH_SMEM (FTILE*5*2)         // 87040 B

__global__ __launch_bounds__(128, 1)
void flash_h(const __half* __restrict__ QKV, __half* __restrict__ O) {
    extern __shared__ char fsm[];
    const uint32_t sb = smem_u32(fsm);
    const uint32_t KsA[2] = {sb,              sb + 2*FTILE*2};
    const uint32_t VsA[2] = {sb + FTILE*2,    sb + 3*FTILE*2};
    const uint32_t QsA    =  sb + 4*FTILE*2;

    const int tid = threadIdx.x;
    const int w = tid >> 5, lane = tid & 31;
    const int g = lane >> 2, tig = lane & 3;
    const int qb  = blockIdx.x;               // 0..31
    const int bh  = blockIdx.y;               // 0..63
    const int b   = bh >> 5;
    const int h   = bh & 31;
    const int kvh = h >> 2;                   // GROUPS=4 consecutive
    const int qm0 = qb * 64;

    const __half* base = QKV + (size_t)b * SEQ * QKVW;
    const __half* Qb = base + h * 128;
    const __half* Kb = base + HID + kvh * 128;
    const __half* Vb = base + HID + KVD + kvh * 128;

    // Q tile: 64 rows x 128 halves = 1024 chunks
#pragma unroll
    for (int j = 0; j < 8; j++) {
        int ci = tid + j * 128;
        int r = ci >> 4, c = ci & 15;
        cp_async16(QsA + (uint32_t)(r * (FQS*2) + c * 16),
                   Qb + (size_t)(qm0 + r) * QKVW + c * 8);
    }
    cp_commit();

    auto load_kv = [&](int s, int kt) {
#pragma unroll
        for (int j = 0; j < 16; j++) {
            int ci = tid + j * 128;
            bool isK = ci < 1024;
            int li = isK ? ci : ci - 1024;
            int r = li >> 4, c = li & 15;
            uint32_t dst = (isK ? KsA[s] : VsA[s]) + (uint32_t)(r * (FQS*2) + c * 16);
            const __half* src = (isK ? Kb : Vb) + (size_t)(kt * 64 + r) * QKVW + c * 8;
            cp_async16(dst, src);
        }
        cp_commit();
    };

    load_kv(0, 0);

    cp_wait<1>();            // Q loaded (KV0 may still be in flight)
    __syncthreads();

    // Q fragments (this warp's 16 rows), persistent across the K-loop
    uint32_t qf[8][4];
#pragma unroll
    for (int kg = 0; kg < 8; kg++) {
        uint32_t row = (uint32_t)(w * 16 + (lane & 7) + ((lane >> 3) & 1) * 8);
        uint32_t col = (uint32_t)(kg * 16 + ((lane >> 4) & 1) * 8);
        ldsm_x4(qf[kg], QsA + row * (FQS*2) + col * 2);
    }

    float oacc[16][4];
#pragma unroll
    for (int i = 0; i < 16; i++)
#pragma unroll
        for (int v = 0; v < 4; v++) oacc[i][v] = 0.f;
    float m0 = -1e30f, m1 = -1e30f, l0 = 0.f, l1 = 0.f;
    const float scale = 0.08838834764831845f;  // 1/sqrt(128)

    for (int kj = 0; kj <= qb; kj++) {
        const int bf = kj & 1;
        if (kj < qb) load_kv(bf ^ 1, kj + 1);
        else cp_commit();
        cp_wait<1>();         // current tile's loads complete
        __syncthreads();

        // ---- S = Q K^T ----
        float sacc[8][4];
#pragma unroll
        for (int nt = 0; nt < 8; nt++)
#pragma unroll
            for (int v = 0; v < 4; v++) sacc[nt][v] = 0.f;

#pragma unroll
        for (int kg = 0; kg < 8; kg++) {
            uint32_t kf[8][2];
#pragma unroll
            for (int np = 0; np < 4; np++) {
                uint32_t row = (uint32_t)(np * 16 + (lane & 7) + ((lane >> 4) & 1) * 8);
                uint32_t col = (uint32_t)(kg * 16 + ((lane >> 3) & 1) * 8);
                uint32_t t[4];
                ldsm_x4(t, KsA[bf] + row * (FQS*2) + col * 2);
                kf[np*2][0] = t[0]; kf[np*2][1] = t[1];
                kf[np*2+1][0] = t[2]; kf[np*2+1][1] = t[3];
            }
#pragma unroll
            for (int nt = 0; nt < 8; nt++)
                mma_f16(sacc[nt], qf[kg], kf[nt]);
        }

        // ---- scale + causal mask ----
#pragma unroll
        for (int nt = 0; nt < 8; nt++)
#pragma unroll
            for (int v = 0; v < 4; v++) sacc[nt][v] *= scale;

        const int q0 = qm0 + w * 16 + g;
        const int q1 = q0 + 8;
        if (kj == qb) {
#pragma unroll
            for (int nt = 0; nt < 8; nt++) {
                int k0 = kj * 64 + nt * 8 + tig * 2;
                if (k0     > q0) sacc[nt][0] = -1e30f;
                if (k0 + 1 > q0) sacc[nt][1] = -1e30f;
                if (k0     > q1) sacc[nt][2] = -1e30f;
                if (k0 + 1 > q1) sacc[nt][3] = -1e30f;
            }
        }

        // ---- online softmax ----
        float rm0 = -1e30f, rm1 = -1e30f;
#pragma unroll
        for (int nt = 0; nt < 8; nt++) {
            rm0 = fmaxf(rm0, fmaxf(sacc[nt][0], sacc[nt][1]));
            rm1 = fmaxf(rm1, fmaxf(sacc[nt][2], sacc[nt][3]));
        }
        rm0 = fmaxf(rm0, __shfl_xor_sync(0xffffffffu, rm0, 1));
        rm0 = fmaxf(rm0, __shfl_xor_sync(0xffffffffu, rm0, 2));
        rm1 = fmaxf(rm1, __shfl_xor_sync(0xffffffffu, rm1, 1));
        rm1 = fmaxf(rm1, __shfl_xor_sync(0xffffffffu, rm1, 2));

        float mn0 = fmaxf(m0, rm0), mn1 = fmaxf(m1, rm1);
        float a0 = __expf(m0 - mn0), a1 = __expf(m1 - mn1);
        float rs0 = 0.f, rs1 = 0.f;
#pragma unroll
        for (int nt = 0; nt < 8; nt++) {
            sacc[nt][0] = __expf(sacc[nt][0] - mn0); rs0 += sacc[nt][0];
            sacc[nt][1] = __expf(sacc[nt][1] - mn0); rs0 += sacc[nt][1];
            sacc[nt][2] = __expf(sacc[nt][2] - mn1); rs1 += sacc[nt][2];
            sacc[nt][3] = __expf(sacc[nt][3] - mn1); rs1 += sacc[nt][3];
        }
        rs0 += __shfl_xor_sync(0xffffffffu, rs0, 1);
        rs0 += __shfl_xor_sync(0xffffffffu, rs0, 2);
        rs1 += __shfl_xor_sync(0xffffffffu, rs1, 1);
        rs1 += __shfl_xor_sync(0xffffffffu, rs1, 2);

        l0 = l0 * a0 + rs0;
        l1 = l1 * a1 + rs1;
        m0 = mn0; m1 = mn1;

#pragma unroll
        for (int nt = 0; nt < 16; nt++) {
            oacc[nt][0] *= a0; oacc[nt][1] *= a0;
            oacc[nt][2] *= a1; oacc[nt][3] *= a1;
        }

        // ---- P -> fp16 in registers ----
        uint32_t pf[8][2];
#pragma unroll
        for (int nt = 0; nt < 8; nt++) {
            pf[nt][0] = pack_h2(sacc[nt][0], sacc[nt][1]);   // row g
            pf[nt][1] = pack_h2(sacc[nt][2], sacc[nt][3]);   // row g+8
        }

        // ---- O += P @ V ----
#pragma unroll
        for (int kg = 0; kg < 4; kg++) {
            uint32_t pa[4] = { pf[2*kg][0], pf[2*kg][1], pf[2*kg+1][0], pf[2*kg+1][1] };
#pragma unroll
            for (int dp = 0; dp < 8; dp++) {
                uint32_t row = (uint32_t)(kg * 16 + (lane & 7) + ((lane >> 3) & 1) * 8);
                uint32_t col = (uint32_t)(dp * 16 + ((lane >> 4) & 1) * 8);
                uint32_t t[4];
                ldsm_x4t(t, VsA[bf] + row * (FQS*2) + col * 2);
                uint32_t b0[2] = { t[0], t[1] };
                uint32_t b1[2] = { t[2], t[3] };
                mma_f16(oacc[dp*2],   pa, b0);
                mma_f16(oacc[dp*2+1], pa, b1);
            }
        }
        __syncthreads();   // all warps done with buf before it is refilled
    }

    // ---- normalize + store fp16 O [MTOT, HID] ----
    float il0 = 1.f / l0, il1 = 1.f / l1;
    size_t ro0 = ((size_t)(b * SEQ + qm0 + w * 16 + g)) * HID + (size_t)h * 128;
    size_t ro1 = ro0 + (size_t)8 * HID;
#pragma unroll
    for (int nt = 0; nt < 16; nt++) {
        int c = nt * 8 + tig * 2;
        *(__half2*)&O[ro0 + c] = __floats2half2_rn(oacc[nt][0] * il0, oacc[nt][1] * il0);
        *(__half2*)&O[ro1 + c] = __floats2half2_rn(oacc[nt][2] * il1, oacc[nt][3] * il1);
    }
}

// ---------------- launch ----------------
extern "C" void kernel_launch(void* const* d_in, const int* in_sizes, int n_in,
                              void* d_out, int out_size) {
    const float* hidden = (const float*)d_in[0];
    const int*   pos    = (const int*)d_in[1];
    const float* Wq     = (const float*)d_in[2];
    const float* Wk     = (const float*)d_in[3];
    const float* Wv     = (const float*)d_in[4];
    const float* Wo     = (const float*)d_in[5];
    float* out = (float*)d_out;

    __half *pAh, *pWh, *pWoh, *pQKV, *pOh;
    float *pc, *ps;
    cudaGetSymbolAddress((void**)&pAh,  g_Ah);
    cudaGetSymbolAddress((void**)&pWh,  g_Wh);
    cudaGetSymbolAddress((void**)&pWoh, g_Woh);
    cudaGetSymbolAddress((void**)&pQKV, g_QKVh);
    cudaGetSymbolAddress((void**)&pOh,  g_Oh);
    cudaGetSymbolAddress((void**)&pc,   g_cos);
    cudaGetSymbolAddress((void**)&ps,   g_sin);

    cudaFuncSetAttribute(gemm_h<true>,
                         cudaFuncAttributeMaxDynamicSharedMemorySize, GEMM_SMEM);
    cudaFuncSetAttribute(gemm_h<false>,
                         cudaFuncAttributeMaxDynamicSharedMemorySize, GEMM_SMEM);
    cudaFuncSetAttribute(flash_h,
                         cudaFuncAttributeMaxDynamicSharedMemorySize, FLASH_SMEM);

    // launch 1: fused fp32 -> fp16 converts (hidden + 4 weights, packed Wq|Wk|Wv)
    {
        F2HArgs a;
        int nHid = (MTOT * HID) / 8, nQ = (HID * HID) / 8, nKV = (KVD * HID) / 8;
        a.src[0] = (const float4*)hidden; a.dst[0] = (uint4*)pAh;
        a.src[1] = (const float4*)Wq;     a.dst[1] = (uint4*)pWh;
        a.src[2] = (const float4*)Wk;     a.dst[2] = (uint4*)(pWh + (size_t)HID * HID);
        a.src[3] = (const float4*)Wv;     a.dst[3] = (uint4*)(pWh + (size_t)(HID + KVD) * HID);
        a.src[4] = (const float4*)Wo;     a.dst[4] = (uint4*)pWoh;
        a.cum[0] = 0;
        a.cum[1] = nHid;
        a.cum[2] = a.cum[1] + nQ;
        a.cum[3] = a.cum[2] + nKV;
        a.cum[4] = a.cum[3] + nKV;
        a.cum[5] = a.cum[4] + nQ;
        f2h_all_kernel<<<CDIV(a.cum[5], 256), 256>>>(a);
    }

    // launch 2: RoPE tables (independent of GEMM; only needs pos)
    rope_table_kernel<<<SEQ, 64>>>(pos, pc, ps);

    // launch 3 (ncu captures this): fused QKV projection
    dim3 gqkv(QKVW / GBN, MTOT / GBM);       // (24, 32) = 768 blocks
    gemm_h<true><<<gqkv, 256, GEMM_SMEM>>>(pAh, pWh, pQKV, QKVW, HID);

    // launches 4-5: RoPE on packed buffer (Q cols 0.., K cols HID..)
    int tq = MTOT * NH * 64;
    int tk = MTOT * KVH * 64;
    rope_qkv_kernel<<<CDIV(tq, 256), 256>>>(pQKV, pc, ps, NH, 0, tq);
    rope_qkv_kernel<<<CDIV(tk, 256), 256>>>(pQKV, pc, ps, KVH, HID, tk);

    // launch 6: attention
    dim3 gf(SEQ / 64, BATCH * NH);           // (32, 64)
    flash_h<<<gf, 128, FLASH_SMEM>>>(pQKV, pOh);

    // launch 7: output projection -> fp32 d_out
    dim3 go(HID / GBN, MTOT / GBM);          // (16, 32)
    gemm_h<false><<<go, 256, GEMM_SMEM>>>(pOh, pWoh, out, HID, HID);
}